// round 2
// baseline (speedup 1.0000x reference)
#include <cuda_runtime.h>
#include <cuda_bf16.h>
#include <cstdint>

// out[b,i,j] = softmax_j( exp( exp(-||x_bi - x_bj||^2 * p) ) ), B=128, K=1024.
//
// R2 design:
//  - One block per (b, 16-row tile). 256 threads, 8 warps.
//  - Warp w owns columns j in [w*128, w*128+128); lane owns 4 CONSECUTIVE j
//    (c-points live in registers for the whole block -> no per-element LDS,
//    and stores are STG.128).
//  - Inner exp: single MUFU EX2 per element (arg pre-scaled by -p*log2e,
//    with ||x||^2 * q staged in smem so the arg is one FMA).
//  - Outer exp: NO second MUFU. e^A = (Taylor4(A/4))^4 on A in (0,1],
//    rel err <= 4.2e-5. Evaluated in packed f32x2 (2 elems/instr).
//  - Row sums: intra-warp shuffle reduce -> smem [16][8] -> 16 threads
//    compute 1/sum -> packed scale -> STG.128.

static constexpr int K = 1024;
static constexpr int THREADS = 256;
static constexpr int ROWS = 16;

#define F32X2_FMA(d, a, b, c) \
    asm("fma.rn.f32x2 %0, %1, %2, %3;" : "=l"(d) : "l"(a), "l"(b), "l"(c))
#define F32X2_MUL(d, a, b) \
    asm("mul.rn.f32x2 %0, %1, %2;" : "=l"(d) : "l"(a), "l"(b))
#define F32X2_ADD(d, a, b) \
    asm("add.rn.f32x2 %0, %1, %2;" : "=l"(d) : "l"(a), "l"(b))

__device__ __forceinline__ uint64_t f32x2_pack(float lo, float hi) {
    uint64_t r;
    asm("mov.b64 %0, {%1, %2};" : "=l"(r) : "f"(lo), "f"(hi));
    return r;
}
__device__ __forceinline__ void f32x2_unpack(float& lo, float& hi, uint64_t v) {
    asm("mov.b64 {%0, %1}, %2;" : "=f"(lo), "=f"(hi) : "l"(v));
}
__device__ __forceinline__ float ex2f(float x) {
    float r;
    asm("ex2.approx.f32 %0, %1;" : "=f"(r) : "f"(x));
    return r;
}

__global__ void __launch_bounds__(THREADS, 2)
adjacency_softmax_kernel(const float* __restrict__ coords,
                         const float* __restrict__ prec,
                         float* __restrict__ out)
{
    __shared__ float4 pk[K];            // (x, y, z, ||x||^2 * q), q = -p*log2e
    __shared__ float  wsum[ROWS][8];    // per-warp row partial sums
    __shared__ float  inv_s[ROWS];

    const int b    = blockIdx.x >> 6;
    const int row0 = (blockIdx.x & 63) << 4;   // local row base within batch
    const int tid  = threadIdx.x;

    const float p = prec[0];
    const float q = -p * 1.4426950408889634f;  // fold log2e into the exp arg

    // Stage all K points of this batch into smem with pre-scaled norm.
    const float* cb = coords + (size_t)b * K * 3;
    #pragma unroll
    for (int j = tid; j < K; j += THREADS) {
        float x = cb[j * 3 + 0];
        float y = cb[j * 3 + 1];
        float z = cb[j * 3 + 2];
        pk[j] = make_float4(x, y, z, (x * x + y * y + z * z) * q);
    }
    __syncthreads();

    const int wid  = tid >> 5;
    const int lane = tid & 31;
    const int jb   = (wid << 7) + (lane << 2);   // 4 consecutive columns per lane

    // Column points (fixed for the whole block) -> registers, packed in pairs.
    const float4 c0 = pk[jb + 0];
    const float4 c1 = pk[jb + 1];
    const float4 c2 = pk[jb + 2];
    const float4 c3 = pk[jb + 3];

    const uint64_t CX01 = f32x2_pack(c0.x, c1.x), CX23 = f32x2_pack(c2.x, c3.x);
    const uint64_t CY01 = f32x2_pack(c0.y, c1.y), CY23 = f32x2_pack(c2.y, c3.y);
    const uint64_t CZ01 = f32x2_pack(c0.z, c1.z), CZ23 = f32x2_pack(c2.z, c3.z);
    const uint64_t CW01 = f32x2_pack(c0.w, c1.w), CW23 = f32x2_pack(c2.w, c3.w);

    const float s2f = -2.0f * q;                      // +2*p*log2e
    const uint64_t S2 = f32x2_pack(s2f, s2f);

    // Taylor coefficients for e^(A/4), A in (0,1].
    const uint64_t K4 = f32x2_pack(1.6276042e-4f, 1.6276042e-4f);  // 1/6144
    const uint64_t K3 = f32x2_pack(2.6041667e-3f, 2.6041667e-3f);  // 1/384
    const uint64_t K2 = f32x2_pack(0.03125f,      0.03125f);       // 1/32
    const uint64_t K1 = f32x2_pack(0.25f,         0.25f);
    const uint64_t K0 = f32x2_pack(1.0f,          1.0f);

    uint64_t v01[ROWS], v23[ROWS];   // unnormalized values, packed pairs

    #pragma unroll
    for (int r = 0; r < ROWS; r++) {
        const float4 a = pk[row0 + r];              // broadcast LDS
        const uint64_t AX  = f32x2_pack(a.x, a.x);
        const uint64_t AY  = f32x2_pack(a.y, a.y);
        const uint64_t AZ  = f32x2_pack(a.z, a.z);
        const uint64_t AWQ = f32x2_pack(a.w, a.w);

        // arg = (||a||^2 + ||c||^2)*q + dot * (2*p*log2e)  == -d*p*log2e
        uint64_t D01, D23, T01, T23;
        F32X2_MUL(D01, CX01, AX);
        F32X2_MUL(D23, CX23, AX);
        F32X2_FMA(D01, CY01, AY, D01);
        F32X2_FMA(D23, CY23, AY, D23);
        F32X2_FMA(D01, CZ01, AZ, D01);
        F32X2_FMA(D23, CZ23, AZ, D23);
        F32X2_ADD(T01, AWQ, CW01);
        F32X2_ADD(T23, AWQ, CW23);
        F32X2_FMA(T01, D01, S2, T01);
        F32X2_FMA(T23, D23, S2, T23);

        // Inner exp: one EX2 per element (the only MUFU op per element).
        float t0, t1, t2, t3;
        f32x2_unpack(t0, t1, T01);
        f32x2_unpack(t2, t3, T23);
        const uint64_t E01 = f32x2_pack(ex2f(t0), ex2f(t1));
        const uint64_t E23 = f32x2_pack(ex2f(t2), ex2f(t3));

        // Outer exp: e^A = (Taylor4(A/4))^4, packed.
        uint64_t P01, P23;
        F32X2_FMA(P01, K4, E01, K3);
        F32X2_FMA(P23, K4, E23, K3);
        F32X2_FMA(P01, P01, E01, K2);
        F32X2_FMA(P23, P23, E23, K2);
        F32X2_FMA(P01, P01, E01, K1);
        F32X2_FMA(P23, P23, E23, K1);
        F32X2_FMA(P01, P01, E01, K0);
        F32X2_FMA(P23, P23, E23, K0);
        F32X2_MUL(P01, P01, P01);
        F32X2_MUL(P23, P23, P23);
        F32X2_MUL(P01, P01, P01);
        F32X2_MUL(P23, P23, P23);

        v01[r] = P01;
        v23[r] = P23;

        // Lane partial row sum -> warp reduce.
        uint64_t SP;
        F32X2_ADD(SP, P01, P23);
        float slo, shi;
        f32x2_unpack(slo, shi, SP);
        float s = slo + shi;
        #pragma unroll
        for (int o = 16; o > 0; o >>= 1)
            s += __shfl_xor_sync(0xFFFFFFFFu, s, o);
        if (lane == 0) wsum[r][wid] = s;
    }

    __syncthreads();

    if (tid < ROWS) {
        float s = 0.0f;
        #pragma unroll
        for (int w = 0; w < 8; w++) s += wsum[tid][w];
        inv_s[tid] = 1.0f / s;
    }
    __syncthreads();

    float4* __restrict__ ob =
        reinterpret_cast<float4*>(out + ((size_t)b * K + row0) * K);
    const int jvec = jb >> 2;   // float4 index within a row

    #pragma unroll
    for (int r = 0; r < ROWS; r++) {
        const float ir = inv_s[r];
        const uint64_t INV = f32x2_pack(ir, ir);
        uint64_t R01, R23;
        F32X2_MUL(R01, v01[r], INV);
        F32X2_MUL(R23, v23[r], INV);
        float f0, f1, f2, f3;
        f32x2_unpack(f0, f1, R01);
        f32x2_unpack(f2, f3, R23);
        ob[(size_t)r * (K / 4) + jvec] = make_float4(f0, f1, f2, f3);
    }
}

extern "C" void kernel_launch(void* const* d_in, const int* in_sizes, int n_in,
                              void* d_out, int out_size)
{
    const float* coords = (const float*)d_in[0];   // [128, 1024, 3] f32
    const float* prec   = (const float*)d_in[1];   // [1] f32
    float* out          = (float*)d_out;           // [128, 1024, 1024] f32

    dim3 grid(128 * (K / ROWS));   // 8192 blocks
    adjacency_softmax_kernel<<<grid, THREADS>>>(coords, prec, out);
}

// round 3
// speedup vs baseline: 1.4406x; 1.4406x over previous
#include <cuda_runtime.h>
#include <cuda_bf16.h>

// out[b,i,j] = softmax_j( exp( exp(-||x_bi - x_bj||^2 * p) ) ), B=128, K=1024.
//
// R3: R1 scalar structure + occupancy fix.
//  - 512 threads (16 warps), 1 row per warp, 16 rows/block, grid = 8192.
//  - pk[j] = (x, y, z, (x^2+y^2+z^2) * -p*log2e) staged in 16 KB smem.
//  - Per element: dot(3 FMA) + arg(add+fma) + EX2 + mul + EX2 + sum add.
//    2x EX2 kept (MUFU floor ~60us; scalar poly replacement costs more FMA
//    than it saves — measured in R2).
//  - 32 values/lane in registers across sum -> normalize (exp evaluated once).
//  - Row sum fully intra-warp (xor shuffle), no smem reduction, no 2nd barrier.
//  - ~60 regs @ 512 thr -> 2 blocks/SM = 32 warps (occ ~50%, was 24%).

static constexpr int K = 1024;
static constexpr int THREADS = 512;
static constexpr int ROWS = 16;
static constexpr float LOG2E = 1.4426950408889634f;

__device__ __forceinline__ float ex2f(float x) {
    float r;
    asm("ex2.approx.f32 %0, %1;" : "=f"(r) : "f"(x));
    return r;
}

__global__ void __launch_bounds__(THREADS, 2)
adjacency_softmax_kernel(const float* __restrict__ coords,
                         const float* __restrict__ prec,
                         float* __restrict__ out)
{
    __shared__ float4 pk[K];   // (x, y, z, ||x||^2 * q), q = -p*log2e

    const int b    = blockIdx.x >> 6;
    const int row0 = (blockIdx.x & 63) << 4;
    const int tid  = threadIdx.x;

    const float p = prec[0];
    const float q = -p * LOG2E;

    const float* cb = coords + (size_t)b * K * 3;
    #pragma unroll
    for (int j = tid; j < K; j += THREADS) {
        float x = cb[j * 3 + 0];
        float y = cb[j * 3 + 1];
        float z = cb[j * 3 + 2];
        pk[j] = make_float4(x, y, z, (x * x + y * y + z * z) * q);
    }
    __syncthreads();

    const int wid  = tid >> 5;
    const int lane = tid & 31;
    const int row  = row0 + wid;          // each warp owns one row

    const float4 a  = pk[row];            // smem broadcast
    const float  s2 = -2.0f * q;          // +2*p*log2e

    float v[32];
    float sum0 = 0.0f, sum1 = 0.0f;       // two chains for ILP

    #pragma unroll
    for (int k = 0; k < 32; k++) {
        const float4 c = pk[k * 32 + lane];          // conflict-free LDS.128
        float dot = a.x * c.x;
        dot = fmaf(a.y, c.y, dot);
        dot = fmaf(a.z, c.z, dot);
        // arg = -(||a-c||^2) * p * log2e
        const float arg = fmaf(dot, s2, a.w + c.w);
        const float A   = ex2f(arg);                 // = exp(-d*p) in (0,1]
        const float e   = ex2f(A * LOG2E);           // = exp(A)
        v[k] = e;
        if (k & 1) sum1 += e; else sum0 += e;
    }

    float s = sum0 + sum1;
    #pragma unroll
    for (int o = 16; o > 0; o >>= 1)
        s += __shfl_xor_sync(0xFFFFFFFFu, s, o);
    const float inv = __fdividef(1.0f, s);

    float* __restrict__ o0 = out + ((size_t)b * K + row) * K;
    #pragma unroll
    for (int k = 0; k < 32; k++)
        o0[k * 32 + lane] = v[k] * inv;   // coalesced 128B per warp-instr
}

extern "C" void kernel_launch(void* const* d_in, const int* in_sizes, int n_in,
                              void* d_out, int out_size)
{
    const float* coords = (const float*)d_in[0];   // [128, 1024, 3] f32
    const float* prec   = (const float*)d_in[1];   // [1] f32
    float* out          = (float*)d_out;           // [128, 1024, 1024] f32

    dim3 grid(128 * (K / ROWS));   // 8192 blocks
    adjacency_softmax_kernel<<<grid, THREADS>>>(coords, prec, out);
}